// round 10
// baseline (speedup 1.0000x reference)
#include <cuda_runtime.h>
#include <cuda_bf16.h>
#include <cstdint>

#define Bb 8
#define Cc 128
#define Nn 10000
#define Kk 16
#define CO 256
#define NT (Bb*Nn)
#define S1 136              // k1 padded smem stride (elements)
#define SK 72               // k2 chunk stride (64 k-elems + 8 pad)

// ---------------------------------------------------------------------------
// Device scratch
// ---------------------------------------------------------------------------
// [W1hi 16384][W1lo 16384][Wphi 16384][Wplo 16384][W2hi 65536][W2lo 65536]
__device__ __align__(16) __nv_bfloat16 g_wimg[4*16384 + 2*65536];
__device__ __align__(16) __nv_bfloat16 g_cat_hi[(size_t)NT*128];   // h only
__device__ __align__(16) __nv_bfloat16 g_cat_lo[(size_t)NT*128];
__device__ __align__(16) float g_q[(size_t)NT*128];

__device__ __forceinline__ void split_bf16(float v, __nv_bfloat16& h, __nv_bfloat16& l) {
    h = __float2bfloat16(v);
    l = __float2bfloat16(v - __bfloat162float(h));
}
__device__ __forceinline__ uint32_t packbf(__nv_bfloat16 a, __nv_bfloat16 b) {
    __nv_bfloat162 p{a, b};
    return *(uint32_t*)&p;
}

// D(16x8,f32) += A(16x16,bf16 row) * B(16x8,bf16 col)
__device__ __forceinline__ void mma_bf16(float* d, const uint32_t* a, const uint32_t* b) {
    asm("mma.sync.aligned.m16n8k16.row.col.f32.bf16.bf16.f32 "
        "{%0,%1,%2,%3}, {%4,%5,%6,%7}, {%8,%9}, {%0,%1,%2,%3};"
        : "+f"(d[0]), "+f"(d[1]), "+f"(d[2]), "+f"(d[3])
        : "r"(a[0]), "r"(a[1]), "r"(a[2]), "r"(a[3]), "r"(b[0]), "r"(b[1]));
}

// ldmatrix x4: 4 8x8 b16 matrices; lane L supplies row (L&15), k-half (L>>4)
__device__ __forceinline__ void ldm4(uint32_t r[4], uint32_t addr) {
    asm volatile("ldmatrix.sync.aligned.m8n8.x4.shared.b16 {%0,%1,%2,%3}, [%4];"
        : "=r"(r[0]), "=r"(r[1]), "=r"(r[2]), "=r"(r[3]) : "r"(addr));
}

__device__ __forceinline__ uint32_t s2u(const void* p) {
    uint32_t a;
    asm("{ .reg .u64 t; cvta.to.shared.u64 t, %1; cvt.u32.u64 %0, t; }" : "=r"(a) : "l"(p));
    return a;
}
__device__ __forceinline__ void cp16(uint32_t dst, const void* src) {
    asm volatile("cp.async.cg.shared.global [%0], [%1], 16;" :: "r"(dst), "l"(src));
}
#define CP_COMMIT() asm volatile("cp.async.commit_group;" ::: "memory")
#define CP_WAIT(N)  asm volatile("cp.async.wait_group %0;" :: "n"(N) : "memory")

// Warp GEMM, tile 32(M) x 32(N), K=128, 3-term hi/lo split (k1, stride S1).
// aWH/aWL/aBH/aBL = smem byte addresses of the 4 operand planes.
__device__ __forceinline__ void gemm_2x4(float acc[2][4][4],
        uint32_t aWH, uint32_t aWL, uint32_t aBH, uint32_t aBL,
        int m0, int n0, int lane)
{
    const int rowA = lane & 15, khalf = (lane >> 4) * 8;
    #pragma unroll
    for (int kk = 0; kk < 8; kk++) {
        const int k0 = kk * 16;
        uint32_t aH[2][4], aL[2][4];
        #pragma unroll
        for (int mi = 0; mi < 2; mi++) {
            uint32_t off = (uint32_t)(((m0 + mi*16 + rowA) * S1 + k0 + khalf) * 2);
            ldm4(aH[mi], aWH + off);
            ldm4(aL[mi], aWL + off);
        }
        #pragma unroll
        for (int np = 0; np < 2; np++) {
            uint32_t off = (uint32_t)(((n0 + np*16 + rowA) * S1 + k0 + khalf) * 2);
            uint32_t bH[4], bL[4];
            ldm4(bH, aBH + off);
            ldm4(bL, aBL + off);
            uint32_t b0H[2] = {bH[0], bH[2]}, b1H[2] = {bH[1], bH[3]};
            uint32_t b0L[2] = {bL[0], bL[2]}, b1L[2] = {bL[1], bL[3]};
            #pragma unroll
            for (int mi = 0; mi < 2; mi++) {
                mma_bf16(acc[mi][2*np],   aH[mi], b0H);
                mma_bf16(acc[mi][2*np],   aH[mi], b0L);
                mma_bf16(acc[mi][2*np],   aL[mi], b0H);
                mma_bf16(acc[mi][2*np+1], aH[mi], b1H);
                mma_bf16(acc[mi][2*np+1], aH[mi], b1L);
                mma_bf16(acc[mi][2*np+1], aL[mi], b1H);
            }
        }
    }
}

// ---------------------------------------------------------------------------
// kw: one-time split of weights into bf16 hi/lo global images
// ---------------------------------------------------------------------------
__global__ void kw(const float* __restrict__ W1, const float* __restrict__ Wp,
                   const float* __restrict__ W2) {
    int t = blockIdx.x * 256 + threadIdx.x;     // 98304
    __nv_bfloat16 h, l;
    if (t < 16384) {
        split_bf16(W1[t], h, l);
        g_wimg[t] = h; g_wimg[16384 + t] = l;
    } else if (t < 32768) {
        int e = t - 16384;
        split_bf16(Wp[e], h, l);
        g_wimg[32768 + e] = h; g_wimg[49152 + e] = l;
    } else {
        int e = t - 32768;
        split_bf16(W2[e], h, l);
        g_wimg[65536 + e] = h; g_wimg[131072 + e] = l;
    }
}

// ---------------------------------------------------------------------------
// k1: per 128-node tile: h = relu(W1@x+b1); q = relu(Wp@h+bp)
//     h -> g_cat (bf16 hi/lo), q -> g_q (fp32). 512 threads, 16 warps.
// ---------------------------------------------------------------------------
__global__ __launch_bounds__(512, 1)
void k1(const float* __restrict__ x, const float* __restrict__ b1v,
        const float* __restrict__ bpv)
{
    extern __shared__ unsigned char sm[];
    const uint32_t sbu = s2u(sm);
    int* xb = (int*)sm;
    __nv_bfloat16* WH = (__nv_bfloat16*)(sm + 512);
    __nv_bfloat16* WL = WH + 128*S1;
    __nv_bfloat16* BH = (__nv_bfloat16*)(sm + 512 + 69632);
    __nv_bfloat16* BL = BH + 128*S1;
    float* Q = (float*)BH;                 // overlay after GEMM2 (stride 132)
    const uint32_t aWH = sbu + 512, aWL = aWH + 128*S1*2;
    const uint32_t aBH = sbu + 512 + 69632, aBL = aBH + 128*S1*2;

    const int tid = threadIdx.x, lane = tid & 31, wid = tid >> 5;
    const int r = lane >> 2, c = (lane & 3) * 2;
    const int m0 = (wid >> 2) * 32, n0 = (wid & 3) * 32;
    const int col0 = blockIdx.x * 128;

    if (tid < 128) {
        int col = col0 + tid, b = col / Nn;
        xb[tid] = b * (Cc * Nn) + (col - b * Nn);
    }
    {   // W1 hi/lo -> smem
        const uint32_t* sH = (const uint32_t*)g_wimg;
        const uint32_t* sL = sH + 8192;
        uint32_t* dH = (uint32_t*)WH;
        uint32_t* dL = (uint32_t*)WL;
        #pragma unroll 4
        for (int i = tid; i < 8192; i += 512) {
            int m = i >> 6, w = i & 63;
            dH[m*68 + w] = sH[i];
            dL[m*68 + w] = sL[i];
        }
    }
    __syncthreads();

    // x tile -> B planes (node-major, split)
    for (int i = tid; i < 16384; i += 512) {
        int j = i & 127, ch = i >> 7;
        float v = x[xb[j] + ch * Nn];
        __nv_bfloat16 h, l; split_bf16(v, h, l);
        BH[j*S1 + ch] = h;
        BL[j*S1 + ch] = l;
    }
    __syncthreads();

    float acc[2][4][4];
    #pragma unroll
    for (int i = 0; i < 2; i++)
        #pragma unroll
        for (int j = 0; j < 4; j++)
            #pragma unroll
            for (int v = 0; v < 4; v++) acc[i][j][v] = 0.f;

    gemm_2x4(acc, aWH, aWL, aBH, aBL, m0, n0, lane);
    __syncthreads();

    // Epilogue 1: h -> B planes ; Wp -> WA
    #pragma unroll
    for (int mi = 0; mi < 2; mi++) {
        int mr = m0 + mi*16 + r;
        float bias_a = b1v[mr], bias_b = b1v[mr + 8];
        #pragma unroll
        for (int ni = 0; ni < 4; ni++) {
            int nc = n0 + ni*8 + c;
            __nv_bfloat16 h, l;
            float v;
            v = fmaxf(acc[mi][ni][0] + bias_a, 0.f); split_bf16(v, h, l);
            BH[nc*S1 + mr] = h;       BL[nc*S1 + mr] = l;
            v = fmaxf(acc[mi][ni][1] + bias_a, 0.f); split_bf16(v, h, l);
            BH[(nc+1)*S1 + mr] = h;   BL[(nc+1)*S1 + mr] = l;
            v = fmaxf(acc[mi][ni][2] + bias_b, 0.f); split_bf16(v, h, l);
            BH[nc*S1 + mr+8] = h;     BL[nc*S1 + mr+8] = l;
            v = fmaxf(acc[mi][ni][3] + bias_b, 0.f); split_bf16(v, h, l);
            BH[(nc+1)*S1 + mr+8] = h; BL[(nc+1)*S1 + mr+8] = l;
        }
    }
    {   // Wp hi/lo -> WA
        const uint32_t* sH = (const uint32_t*)(g_wimg + 32768);
        const uint32_t* sL = (const uint32_t*)(g_wimg + 49152);
        uint32_t* dH = (uint32_t*)WH;
        uint32_t* dL = (uint32_t*)WL;
        #pragma unroll 4
        for (int i = tid; i < 8192; i += 512) {
            int m = i >> 6, w = i & 63;
            dH[m*68 + w] = sH[i];
            dL[m*68 + w] = sL[i];
        }
    }
    __syncthreads();

    // h rows -> g_cat (coalesced uint4)
    for (int i = tid; i < 2048; i += 512) {
        int j = i >> 4, v = i & 15;
        ((uint4*)(g_cat_hi + (size_t)(col0 + j) * 128))[v] = ((const uint4*)(BH + j*S1))[v];
        ((uint4*)(g_cat_lo + (size_t)(col0 + j) * 128))[v] = ((const uint4*)(BL + j*S1))[v];
    }

    #pragma unroll
    for (int i = 0; i < 2; i++)
        #pragma unroll
        for (int j = 0; j < 4; j++)
            #pragma unroll
            for (int v = 0; v < 4; v++) acc[i][j][v] = 0.f;

    gemm_2x4(acc, aWH, aWL, aBH, aBL, m0, n0, lane);
    __syncthreads();

    // Epilogue 2: q -> staging (fp32, stride 132)
    #pragma unroll
    for (int mi = 0; mi < 2; mi++) {
        int mr = m0 + mi*16 + r;
        float bias_a = bpv[mr], bias_b = bpv[mr + 8];
        #pragma unroll
        for (int ni = 0; ni < 4; ni++) {
            int nc = n0 + ni*8 + c;
            Q[nc*132 + mr]       = fmaxf(acc[mi][ni][0] + bias_a, 0.f);
            Q[(nc+1)*132 + mr]   = fmaxf(acc[mi][ni][1] + bias_a, 0.f);
            Q[nc*132 + mr+8]     = fmaxf(acc[mi][ni][2] + bias_b, 0.f);
            Q[(nc+1)*132 + mr+8] = fmaxf(acc[mi][ni][3] + bias_b, 0.f);
        }
    }
    __syncthreads();

    for (int i = tid; i < 4096; i += 512) {
        int j = i >> 5, v = i & 31;
        ((float4*)(g_q + (size_t)(col0 + j) * 128))[v] = ((const float4*)(Q + j*132))[v];
    }
}

// ---------------------------------------------------------------------------
// k2: out = relu(W2 @ cat + b2). M=256, N=128/block. K=256 in 4 chunks of 64,
//     double-buffered cp.async; chunks 2,3 B operand GATHERED in-kernel from g_q.
// ---------------------------------------------------------------------------
#define K2_STAGE 110592
#define K2_AH 0
#define K2_AL 36864
#define K2_BH 73728
#define K2_BL 92160

__device__ __forceinline__ void k2_load_a(uint32_t sbu, int stage, int ks, int tid) {
    const uint32_t base = sbu + stage * K2_STAGE;
    const __nv_bfloat16* srcH = g_wimg + 65536;
    const __nv_bfloat16* srcL = g_wimg + 131072;
    #pragma unroll
    for (int t = 0; t < 4; t++) {
        int i = tid + t * 512;           // 0..2047
        int m = i >> 3, ch = i & 7;
        int so = m * 256 + ks * 64 + ch * 8;
        uint32_t doff = (uint32_t)(m * SK + ch * 8) * 2;
        cp16(base + K2_AH + doff, srcH + so);
        cp16(base + K2_AL + doff, srcL + so);
    }
}
__device__ __forceinline__ void k2_load_b_cat(uint32_t sbu, int stage, int ks,
                                              int col0, int tid) {
    const uint32_t base = sbu + stage * K2_STAGE;
    #pragma unroll
    for (int t = 0; t < 2; t++) {
        int i = tid + t * 512;           // 0..1023
        int j = i >> 3, ch = i & 7;
        size_t so = (size_t)(col0 + j) * 128 + ks * 64 + ch * 8;
        uint32_t doff = (uint32_t)(j * SK + ch * 8) * 2;
        cp16(base + K2_BH + doff, g_cat_hi + so);
        cp16(base + K2_BL + doff, g_cat_lo + so);
    }
}

// gather-max 128 nodes x 128 ch into packed bf16 hi/lo regs.
__device__ __forceinline__ void k2_gather(const int* __restrict__ eidx, int col0,
                                          int wid, int lane,
                                          uint32_t gh[8][2], uint32_t gl[8][2]) {
    #pragma unroll
    for (int t = 0; t < 8; t++) {
        int col = col0 + wid + 16 * t;
        int b = col / Nn;
        const float* qb = g_q + (size_t)b * Nn * 128;
        int id = 0;
        if (lane < Kk) id = eidx[col * Kk + lane];
        float4 m = make_float4(0.f, 0.f, 0.f, 0.f);   // relu output >= 0
        #pragma unroll
        for (int k = 0; k < Kk; k++) {
            int nb = __shfl_sync(0xffffffffu, id, k);
            float4 v = ((const float4*)(qb + (size_t)nb * 128))[lane];
            m.x = fmaxf(m.x, v.x); m.y = fmaxf(m.y, v.y);
            m.z = fmaxf(m.z, v.z); m.w = fmaxf(m.w, v.w);
        }
        __nv_bfloat16 h0,l0,h1,l1,h2,l2,h3,l3;
        split_bf16(m.x, h0, l0); split_bf16(m.y, h1, l1);
        split_bf16(m.z, h2, l2); split_bf16(m.w, h3, l3);
        gh[t][0] = packbf(h0, h1); gh[t][1] = packbf(h2, h3);
        gl[t][0] = packbf(l0, l1); gl[t][1] = packbf(l2, l3);
    }
}

// lanes 0-15 hold chunk2 (half=0), lanes 16-31 chunk3 (half=1)
__device__ __forceinline__ void k2_store_gather(unsigned char* sm, int stage, int half,
                                                const uint32_t gh[8][2],
                                                const uint32_t gl[8][2],
                                                int wid, int lane) {
    if ((lane >> 4) != half) return;
    const int kloc = (lane & 15) * 4;
    unsigned char* BH = sm + stage * K2_STAGE + K2_BH;
    unsigned char* BL = sm + stage * K2_STAGE + K2_BL;
    #pragma unroll
    for (int t = 0; t < 8; t++) {
        int j = wid + 16 * t;
        *(uint2*)(BH + (j * SK + kloc) * 2) = make_uint2(gh[t][0], gh[t][1]);
        *(uint2*)(BL + (j * SK + kloc) * 2) = make_uint2(gl[t][0], gl[t][1]);
    }
}

__device__ __forceinline__ void k2_gemm(float acc[2][8][4], uint32_t sbu,
                                        int stage, int m0, int n0, int lane) {
    const uint32_t st = sbu + stage * K2_STAGE;
    const int rowA = lane & 15, khalf = (lane >> 4) * 8;
    #pragma unroll
    for (int kk = 0; kk < 4; kk++) {
        const int k0 = kk * 16;
        uint32_t aH[2][4], aL[2][4];
        #pragma unroll
        for (int mi = 0; mi < 2; mi++) {
            uint32_t off = (uint32_t)(((m0 + mi*16 + rowA) * SK + k0 + khalf) * 2);
            ldm4(aH[mi], st + K2_AH + off);
            ldm4(aL[mi], st + K2_AL + off);
        }
        #pragma unroll
        for (int np = 0; np < 4; np++) {
            uint32_t off = (uint32_t)(((n0 + np*16 + rowA) * SK + k0 + khalf) * 2);
            uint32_t bH[4], bL[4];
            ldm4(bH, st + K2_BH + off);
            ldm4(bL, st + K2_BL + off);
            uint32_t b0H[2] = {bH[0], bH[2]}, b1H[2] = {bH[1], bH[3]};
            uint32_t b0L[2] = {bL[0], bL[2]}, b1L[2] = {bL[1], bL[3]};
            #pragma unroll
            for (int mi = 0; mi < 2; mi++) {
                mma_bf16(acc[mi][2*np],   aH[mi], b0H);
                mma_bf16(acc[mi][2*np],   aH[mi], b0L);
                mma_bf16(acc[mi][2*np],   aL[mi], b0H);
                mma_bf16(acc[mi][2*np+1], aH[mi], b1H);
                mma_bf16(acc[mi][2*np+1], aH[mi], b1L);
                mma_bf16(acc[mi][2*np+1], aL[mi], b1H);
            }
        }
    }
}

__global__ __launch_bounds__(512)
void k2(const int* __restrict__ eidx, const float* __restrict__ b2v,
        float* __restrict__ out)
{
    extern __shared__ unsigned char sm[];
    const uint32_t sbu = s2u(sm);
    const int tid = threadIdx.x, lane = tid & 31, wid = tid >> 5;
    const int r = lane >> 2, c = (lane & 3) * 2;
    const int m0 = (wid >> 1) * 32, n0 = (wid & 1) * 64;
    const int col0 = blockIdx.x * 128;

    // Prefetch chunks 0,1 (A = W2 slices; B = h from g_cat)
    k2_load_a(sbu, 0, 0, tid); k2_load_b_cat(sbu, 0, 0, col0, tid); CP_COMMIT(); // G0
    k2_load_a(sbu, 1, 1, tid); k2_load_b_cat(sbu, 1, 1, col0, tid); CP_COMMIT(); // G1

    // Gather chunks 2,3 into registers (overlaps G0/G1 arrival)
    uint32_t gh[8][2], gl[8][2];
    k2_gather(eidx, col0, wid, lane, gh, gl);

    float acc[2][8][4];
    #pragma unroll
    for (int i = 0; i < 2; i++)
        #pragma unroll
        for (int j = 0; j < 8; j++)
            #pragma unroll
            for (int v = 0; v < 4; v++) acc[i][j][v] = 0.f;

    CP_WAIT(1); __syncthreads();           // G0 done
    k2_gemm(acc, sbu, 0, m0, n0, lane);    // chunk 0
    __syncthreads();                       // stage0 B free

    k2_store_gather(sm, 0, 0, gh, gl, wid, lane);   // chunk2 -> B(st0)
    k2_load_a(sbu, 0, 2, tid); CP_COMMIT();          // G2 (A only)
    CP_WAIT(1); __syncthreads();           // G1 done
    k2_gemm(acc, sbu, 1, m0, n0, lane);    // chunk 1
    __syncthreads();                       // stage1 B free

    k2_store_gather(sm, 1, 1, gh, gl, wid, lane);   // chunk3 -> B(st1)
    k2_load_a(sbu, 1, 3, tid); CP_COMMIT();          // G3
    CP_WAIT(1); __syncthreads();           // G2 done (+ STS visible)
    k2_gemm(acc, sbu, 0, m0, n0, lane);    // chunk 2
    __syncthreads();
    CP_WAIT(0); __syncthreads();           // G3 done
    k2_gemm(acc, sbu, 1, m0, n0, lane);    // chunk 3

    // Epilogue: bias + relu + direct store, out[b][d][node]
    #pragma unroll
    for (int mi = 0; mi < 2; mi++) {
        int mr = m0 + mi*16 + r;
        float bias_a = b2v[mr], bias_b = b2v[mr + 8];
        #pragma unroll
        for (int ni = 0; ni < 8; ni++) {
            int nc = n0 + ni*8 + c;
            int colA = col0 + nc, colB = colA + 1;
            int ba = colA / Nn, bb = colB / Nn;
            size_t obA = (size_t)ba * CO * Nn + (colA - ba * Nn);
            size_t obB = (size_t)bb * CO * Nn + (colB - bb * Nn);
            out[obA + (size_t)mr * Nn]     = fmaxf(acc[mi][ni][0] + bias_a, 0.f);
            out[obB + (size_t)mr * Nn]     = fmaxf(acc[mi][ni][1] + bias_a, 0.f);
            out[obA + (size_t)(mr+8) * Nn] = fmaxf(acc[mi][ni][2] + bias_b, 0.f);
            out[obB + (size_t)(mr+8) * Nn] = fmaxf(acc[mi][ni][3] + bias_b, 0.f);
        }
    }
}

// ---------------------------------------------------------------------------
extern "C" void kernel_launch(void* const* d_in, const int* in_sizes, int n_in,
                              void* d_out, int out_size)
{
    const float* x  = (const float*)d_in[0];
    const int*   ei = (const int*)  d_in[1];
    const float* W1 = (const float*)d_in[2];
    const float* b1 = (const float*)d_in[3];
    const float* Wp = (const float*)d_in[4];
    const float* bp = (const float*)d_in[5];
    const float* W2 = (const float*)d_in[6];
    const float* b2 = (const float*)d_in[7];
    float* out = (float*)d_out;

    const int s1 = 139776;
    const int s2 = 2 * K2_STAGE;      // 221184
    cudaFuncSetAttribute(k1, cudaFuncAttributeMaxDynamicSharedMemorySize, s1);
    cudaFuncSetAttribute(k2, cudaFuncAttributeMaxDynamicSharedMemorySize, s2);

    kw<<<384, 256>>>(W1, Wp, W2);
    k1<<<NT / 128, 512, s1>>>(x, b1, bp);
    k2<<<NT / 128, 512, s2>>>(ei, b2, out);
}

// round 11
// speedup vs baseline: 1.6743x; 1.6743x over previous
#include <cuda_runtime.h>
#include <cuda_bf16.h>
#include <cuda_fp16.h>
#include <cstdint>

#define Bb 8
#define Cc 128
#define Nn 10000
#define Kk 16
#define CO 256
#define NT (Bb*Nn)
#define S1 136              // k1 padded smem stride (elements)
#define SK 72               // k2 chunk stride (64 k-elems + 8 pad)

// ---------------------------------------------------------------------------
// Device scratch
// ---------------------------------------------------------------------------
// [W1hi 16384][W1lo 16384][Wphi 16384][Wplo 16384]  (bf16 hi/lo, k1 GEMMs)
__device__ __align__(16) __nv_bfloat16 g_wimg[4*16384];
__device__ __align__(16) __half g_w2h[65536];                 // W2 fp16 single
__device__ __align__(16) __half g_cat[(size_t)NT*128];        // h, fp16
__device__ __align__(16) __half g_q[(size_t)NT*128];          // q, fp16

__device__ __forceinline__ void split_bf16(float v, __nv_bfloat16& h, __nv_bfloat16& l) {
    h = __float2bfloat16(v);
    l = __float2bfloat16(v - __bfloat162float(h));
}

// D(16x8,f32) += A(16x16,bf16 row) * B(16x8,bf16 col)
__device__ __forceinline__ void mma_bf16(float* d, const uint32_t* a, const uint32_t* b) {
    asm("mma.sync.aligned.m16n8k16.row.col.f32.bf16.bf16.f32 "
        "{%0,%1,%2,%3}, {%4,%5,%6,%7}, {%8,%9}, {%0,%1,%2,%3};"
        : "+f"(d[0]), "+f"(d[1]), "+f"(d[2]), "+f"(d[3])
        : "r"(a[0]), "r"(a[1]), "r"(a[2]), "r"(a[3]), "r"(b[0]), "r"(b[1]));
}
// D(16x8,f32) += A(16x16,fp16 row) * B(16x8,fp16 col)
__device__ __forceinline__ void mma_f16(float* d, const uint32_t* a, const uint32_t* b) {
    asm("mma.sync.aligned.m16n8k16.row.col.f32.f16.f16.f32 "
        "{%0,%1,%2,%3}, {%4,%5,%6,%7}, {%8,%9}, {%0,%1,%2,%3};"
        : "+f"(d[0]), "+f"(d[1]), "+f"(d[2]), "+f"(d[3])
        : "r"(a[0]), "r"(a[1]), "r"(a[2]), "r"(a[3]), "r"(b[0]), "r"(b[1]));
}

// ldmatrix x4: lane L supplies addr of row (L&15), k-half (L>>4)
__device__ __forceinline__ void ldm4(uint32_t r[4], uint32_t addr) {
    asm volatile("ldmatrix.sync.aligned.m8n8.x4.shared.b16 {%0,%1,%2,%3}, [%4];"
        : "=r"(r[0]), "=r"(r[1]), "=r"(r[2]), "=r"(r[3]) : "r"(addr));
}

__device__ __forceinline__ uint32_t s2u(const void* p) {
    uint32_t a;
    asm("{ .reg .u64 t; cvta.to.shared.u64 t, %1; cvt.u32.u64 %0, t; }" : "=r"(a) : "l"(p));
    return a;
}
__device__ __forceinline__ void cp16(uint32_t dst, const void* src) {
    asm volatile("cp.async.cg.shared.global [%0], [%1], 16;" :: "r"(dst), "l"(src));
}
#define CP_COMMIT() asm volatile("cp.async.commit_group;" ::: "memory")
#define CP_WAIT(N)  asm volatile("cp.async.wait_group %0;" :: "n"(N) : "memory")

// Warp GEMM, tile 32(M) x 32(N), K=128, 3-term hi/lo split (k1, stride S1, scalar LDS).
__device__ __forceinline__ void gemm_2x4(float acc[2][4][4],
        const __nv_bfloat16* WH, const __nv_bfloat16* WL,
        const __nv_bfloat16* BH, const __nv_bfloat16* BL,
        int m0, int n0, int r, int c)
{
    #pragma unroll
    for (int kk = 0; kk < 8; kk++) {
        const int k0 = kk * 16;
        uint32_t aH[2][4], aL[2][4];
        #pragma unroll
        for (int mi = 0; mi < 2; mi++) {
            const __nv_bfloat16* pH = WH + (m0 + mi*16 + r)*S1 + k0 + c;
            const __nv_bfloat16* pL = WL + (m0 + mi*16 + r)*S1 + k0 + c;
            aH[mi][0] = *(const uint32_t*)pH;
            aH[mi][1] = *(const uint32_t*)(pH + 8*S1);
            aH[mi][2] = *(const uint32_t*)(pH + 8);
            aH[mi][3] = *(const uint32_t*)(pH + 8*S1 + 8);
            aL[mi][0] = *(const uint32_t*)pL;
            aL[mi][1] = *(const uint32_t*)(pL + 8*S1);
            aL[mi][2] = *(const uint32_t*)(pL + 8);
            aL[mi][3] = *(const uint32_t*)(pL + 8*S1 + 8);
        }
        #pragma unroll
        for (int ni = 0; ni < 4; ni++) {
            const __nv_bfloat16* pH = BH + (n0 + ni*8 + r)*S1 + k0 + c;
            const __nv_bfloat16* pL = BL + (n0 + ni*8 + r)*S1 + k0 + c;
            uint32_t bH[2], bL[2];
            bH[0] = *(const uint32_t*)pH; bH[1] = *(const uint32_t*)(pH + 8);
            bL[0] = *(const uint32_t*)pL; bL[1] = *(const uint32_t*)(pL + 8);
            #pragma unroll
            for (int mi = 0; mi < 2; mi++) {
                mma_bf16(acc[mi][ni], aH[mi], bH);
                mma_bf16(acc[mi][ni], aH[mi], bL);
                mma_bf16(acc[mi][ni], aL[mi], bH);
            }
        }
    }
}

// ---------------------------------------------------------------------------
// kw: one-time weight preprocessing
// ---------------------------------------------------------------------------
__global__ void kw(const float* __restrict__ W1, const float* __restrict__ Wp,
                   const float* __restrict__ W2) {
    int t = blockIdx.x * 256 + threadIdx.x;     // 98304
    if (t < 16384) {
        __nv_bfloat16 h, l; split_bf16(W1[t], h, l);
        g_wimg[t] = h; g_wimg[16384 + t] = l;
    } else if (t < 32768) {
        int e = t - 16384;
        __nv_bfloat16 h, l; split_bf16(Wp[e], h, l);
        g_wimg[32768 + e] = h; g_wimg[49152 + e] = l;
    } else {
        int e = t - 32768;
        g_w2h[e] = __float2half_rn(W2[e]);
    }
}

// ---------------------------------------------------------------------------
// k1: per 128-node tile: h = relu(W1@x+b1); q = relu(Wp@h+bp)
//     h -> g_cat (fp16), q -> g_q (fp16). 512 threads, 16 warps.
// smem: [xb 512][W hi/lo 69632][B hi/lo 69632][Hf 34816] = 174592
// ---------------------------------------------------------------------------
__global__ __launch_bounds__(512, 1)
void k1(const float* __restrict__ x, const float* __restrict__ b1v,
        const float* __restrict__ bpv)
{
    extern __shared__ unsigned char sm[];
    int* xb = (int*)sm;
    __nv_bfloat16* WH = (__nv_bfloat16*)(sm + 512);
    __nv_bfloat16* WL = WH + 128*S1;
    __nv_bfloat16* BH = (__nv_bfloat16*)(sm + 512 + 69632);
    __nv_bfloat16* BL = BH + 128*S1;
    __half* Hf = (__half*)(sm + 512 + 69632 + 69632);   // [128][136] fp16 h staging
    float* Q = (float*)BH;                 // overlay after GEMM2 (stride 132)

    const int tid = threadIdx.x, lane = tid & 31, wid = tid >> 5;
    const int r = lane >> 2, c = (lane & 3) * 2;
    const int m0 = (wid >> 2) * 32, n0 = (wid & 3) * 32;
    const int col0 = blockIdx.x * 128;

    if (tid < 128) {
        int col = col0 + tid, b = col / Nn;
        xb[tid] = b * (Cc * Nn) + (col - b * Nn);
    }
    {   // W1 hi/lo -> smem
        const uint32_t* sH = (const uint32_t*)g_wimg;
        const uint32_t* sL = sH + 8192;
        uint32_t* dH = (uint32_t*)WH;
        uint32_t* dL = (uint32_t*)WL;
        #pragma unroll 4
        for (int i = tid; i < 8192; i += 512) {
            int m = i >> 6, w = i & 63;
            dH[m*68 + w] = sH[i];
            dL[m*68 + w] = sL[i];
        }
    }
    __syncthreads();

    // x tile -> B planes (node-major, split)
    for (int i = tid; i < 16384; i += 512) {
        int j = i & 127, ch = i >> 7;
        float v = x[xb[j] + ch * Nn];
        __nv_bfloat16 h, l; split_bf16(v, h, l);
        BH[j*S1 + ch] = h;
        BL[j*S1 + ch] = l;
    }
    __syncthreads();

    float acc[2][4][4];
    #pragma unroll
    for (int i = 0; i < 2; i++)
        #pragma unroll
        for (int j = 0; j < 4; j++)
            #pragma unroll
            for (int v = 0; v < 4; v++) acc[i][j][v] = 0.f;

    gemm_2x4(acc, WH, WL, BH, BL, m0, n0, r, c);
    __syncthreads();

    // Epilogue 1: h -> B planes (bf16 hi/lo, GEMM2 operand) + Hf (fp16, cat)
    #pragma unroll
    for (int mi = 0; mi < 2; mi++) {
        int mr = m0 + mi*16 + r;
        float bias_a = b1v[mr], bias_b = b1v[mr + 8];
        #pragma unroll
        for (int ni = 0; ni < 4; ni++) {
            int nc = n0 + ni*8 + c;
            __nv_bfloat16 h, l;
            float v;
            v = fmaxf(acc[mi][ni][0] + bias_a, 0.f); split_bf16(v, h, l);
            BH[nc*S1 + mr] = h;       BL[nc*S1 + mr] = l;
            Hf[nc*136 + mr] = __float2half_rn(v);
            v = fmaxf(acc[mi][ni][1] + bias_a, 0.f); split_bf16(v, h, l);
            BH[(nc+1)*S1 + mr] = h;   BL[(nc+1)*S1 + mr] = l;
            Hf[(nc+1)*136 + mr] = __float2half_rn(v);
            v = fmaxf(acc[mi][ni][2] + bias_b, 0.f); split_bf16(v, h, l);
            BH[nc*S1 + mr+8] = h;     BL[nc*S1 + mr+8] = l;
            Hf[nc*136 + mr+8] = __float2half_rn(v);
            v = fmaxf(acc[mi][ni][3] + bias_b, 0.f); split_bf16(v, h, l);
            BH[(nc+1)*S1 + mr+8] = h; BL[(nc+1)*S1 + mr+8] = l;
            Hf[(nc+1)*136 + mr+8] = __float2half_rn(v);
        }
    }
    {   // Wp hi/lo -> WA
        const uint32_t* sH = (const uint32_t*)(g_wimg + 32768);
        const uint32_t* sL = (const uint32_t*)(g_wimg + 49152);
        uint32_t* dH = (uint32_t*)WH;
        uint32_t* dL = (uint32_t*)WL;
        #pragma unroll 4
        for (int i = tid; i < 8192; i += 512) {
            int m = i >> 6, w = i & 63;
            dH[m*68 + w] = sH[i];
            dL[m*68 + w] = sL[i];
        }
    }
    __syncthreads();

    // h rows -> g_cat (coalesced uint4, fp16)
    for (int i = tid; i < 2048; i += 512) {
        int j = i >> 4, v = i & 15;
        ((uint4*)(g_cat + (size_t)(col0 + j) * 128))[v] = ((const uint4*)(Hf + j*136))[v];
    }

    #pragma unroll
    for (int i = 0; i < 2; i++)
        #pragma unroll
        for (int j = 0; j < 4; j++)
            #pragma unroll
            for (int v = 0; v < 4; v++) acc[i][j][v] = 0.f;

    gemm_2x4(acc, WH, WL, BH, BL, m0, n0, r, c);
    __syncthreads();

    // Epilogue 2: q -> staging (fp32, stride 132)
    #pragma unroll
    for (int mi = 0; mi < 2; mi++) {
        int mr = m0 + mi*16 + r;
        float bias_a = bpv[mr], bias_b = bpv[mr + 8];
        #pragma unroll
        for (int ni = 0; ni < 4; ni++) {
            int nc = n0 + ni*8 + c;
            Q[nc*132 + mr]       = fmaxf(acc[mi][ni][0] + bias_a, 0.f);
            Q[(nc+1)*132 + mr]   = fmaxf(acc[mi][ni][1] + bias_a, 0.f);
            Q[nc*132 + mr+8]     = fmaxf(acc[mi][ni][2] + bias_b, 0.f);
            Q[(nc+1)*132 + mr+8] = fmaxf(acc[mi][ni][3] + bias_b, 0.f);
        }
    }
    __syncthreads();

    // q -> g_q (fp16, coalesced uint2)
    for (int i = tid; i < 4096; i += 512) {
        int j = i >> 5, v = i & 31;
        float4 f = *(const float4*)(Q + j*132 + v*4);
        __half2 p0 = __floats2half2_rn(f.x, f.y);
        __half2 p1 = __floats2half2_rn(f.z, f.w);
        uint2 u = make_uint2(*(uint32_t*)&p0, *(uint32_t*)&p1);
        *(uint2*)(g_q + (size_t)(col0 + j) * 128 + v*4) = u;
    }
}

// ---------------------------------------------------------------------------
// k2: out = relu(W2 @ cat + b2), single-term fp16 MMA.
// M=256, N=128/block. K=256 in 4 chunks of 64, double-buffered cp.async;
// chunks 2,3 B operand gathered in-kernel from g_q (fp16, hmax2).
// stage: [A 256xSK fp16 36864][B 128xSK fp16 18432] = 55296; x2 = 110592
// ---------------------------------------------------------------------------
#define K2_STAGE 55296
#define K2_B 36864

__device__ __forceinline__ void k2_load_a(uint32_t sbu, int stage, int ks, int tid) {
    const uint32_t base = sbu + stage * K2_STAGE;
    #pragma unroll
    for (int t = 0; t < 4; t++) {
        int i = tid + t * 512;           // 0..2047
        int m = i >> 3, ch = i & 7;
        cp16(base + (uint32_t)(m * SK + ch * 8) * 2, g_w2h + m * 256 + ks * 64 + ch * 8);
    }
}
__device__ __forceinline__ void k2_load_b_cat(uint32_t sbu, int stage, int ks,
                                              int col0, int tid) {
    const uint32_t base = sbu + stage * K2_STAGE + K2_B;
    #pragma unroll
    for (int t = 0; t < 2; t++) {
        int i = tid + t * 512;           // 0..1023
        int j = i >> 3, ch = i & 7;
        cp16(base + (uint32_t)(j * SK + ch * 8) * 2,
             g_cat + (size_t)(col0 + j) * 128 + ks * 64 + ch * 8);
    }
}

// gather-max 128 nodes x 128 ch (fp16). Round t: warp gets node wid+16t;
// lane covers ch = lane*4 (uint2 = 4 fp16).
__device__ __forceinline__ void k2_gather(const int* __restrict__ eidx, int col0,
                                          int wid, int lane, uint2 g[8]) {
    #pragma unroll
    for (int t = 0; t < 8; t++) {
        int col = col0 + wid + 16 * t;
        int b = col / Nn;
        const __half* qb = g_q + (size_t)b * Nn * 128;
        int id = 0;
        if (lane < Kk) id = eidx[col * Kk + lane];
        __half2 m0 = __half2{__half(0.f), __half(0.f)}, m1 = m0;   // q >= 0
        #pragma unroll
        for (int k = 0; k < Kk; k++) {
            int nb = __shfl_sync(0xffffffffu, id, k);
            uint2 v = *(const uint2*)(qb + (size_t)nb * 128 + lane * 4);
            m0 = __hmax2(m0, *(__half2*)&v.x);
            m1 = __hmax2(m1, *(__half2*)&v.y);
        }
        g[t] = make_uint2(*(uint32_t*)&m0, *(uint32_t*)&m1);
    }
}

// lanes 0-15 hold chunk2 (half=0), lanes 16-31 chunk3 (half=1)
__device__ __forceinline__ void k2_store_gather(unsigned char* sm, int stage, int half,
                                                const uint2 g[8], int wid, int lane) {
    if ((lane >> 4) != half) return;
    const int kloc = (lane & 15) * 4;
    unsigned char* B = sm + stage * K2_STAGE + K2_B;
    #pragma unroll
    for (int t = 0; t < 8; t++) {
        int j = wid + 16 * t;
        *(uint2*)(B + (j * SK + kloc) * 2) = g[t];
    }
}

// one K=64 chunk, single-term fp16, ldmatrix fragments
__device__ __forceinline__ void k2_gemm(float acc[2][8][4], uint32_t sbu,
                                        int stage, int m0, int n0, int lane) {
    const uint32_t st = sbu + stage * K2_STAGE;
    const int rowA = lane & 15, khalf = (lane >> 4) * 8;
    #pragma unroll
    for (int kk = 0; kk < 4; kk++) {
        const int k0 = kk * 16;
        uint32_t a[2][4];
        #pragma unroll
        for (int mi = 0; mi < 2; mi++)
            ldm4(a[mi], st + (uint32_t)(((m0 + mi*16 + rowA) * SK + k0 + khalf) * 2));
        #pragma unroll
        for (int np = 0; np < 4; np++) {
            uint32_t bm[4];
            ldm4(bm, st + K2_B + (uint32_t)(((n0 + np*16 + rowA) * SK + k0 + khalf) * 2));
            uint32_t b0[2] = {bm[0], bm[2]}, b1[2] = {bm[1], bm[3]};
            #pragma unroll
            for (int mi = 0; mi < 2; mi++) {
                mma_f16(acc[mi][2*np],   a[mi], b0);
                mma_f16(acc[mi][2*np+1], a[mi], b1);
            }
        }
    }
}

__global__ __launch_bounds__(512)
void k2(const int* __restrict__ eidx, const float* __restrict__ b2v,
        float* __restrict__ out)
{
    extern __shared__ unsigned char sm[];
    const uint32_t sbu = s2u(sm);
    const int tid = threadIdx.x, lane = tid & 31, wid = tid >> 5;
    const int r = lane >> 2, c = (lane & 3) * 2;
    const int m0 = (wid >> 1) * 32, n0 = (wid & 1) * 64;
    const int col0 = blockIdx.x * 128;

    // Prefetch chunks 0,1 (A = W2 slices; B = h from g_cat)
    k2_load_a(sbu, 0, 0, tid); k2_load_b_cat(sbu, 0, 0, col0, tid); CP_COMMIT(); // G0
    k2_load_a(sbu, 1, 1, tid); k2_load_b_cat(sbu, 1, 1, col0, tid); CP_COMMIT(); // G1

    // Gather chunks 2,3 into registers (overlaps G0/G1 arrival)
    uint2 g[8];
    k2_gather(eidx, col0, wid, lane, g);

    float acc[2][8][4];
    #pragma unroll
    for (int i = 0; i < 2; i++)
        #pragma unroll
        for (int j = 0; j < 8; j++)
            #pragma unroll
            for (int v = 0; v < 4; v++) acc[i][j][v] = 0.f;

    CP_WAIT(1); __syncthreads();           // G0 done
    k2_gemm(acc, sbu, 0, m0, n0, lane);    // chunk 0
    __syncthreads();                       // stage0 B free

    k2_store_gather(sm, 0, 0, g, wid, lane);   // chunk2 -> B(st0)
    k2_load_a(sbu, 0, 2, tid); CP_COMMIT();    // G2 (A only)
    CP_WAIT(1); __syncthreads();           // G1 done
    k2_gemm(acc, sbu, 1, m0, n0, lane);    // chunk 1
    __syncthreads();                       // stage1 B free

    k2_store_gather(sm, 1, 1, g, wid, lane);   // chunk3 -> B(st1)
    k2_load_a(sbu, 1, 3, tid); CP_COMMIT();    // G3
    CP_WAIT(1); __syncthreads();           // G2 done (+ STS visible)
    k2_gemm(acc, sbu, 0, m0, n0, lane);    // chunk 2
    __syncthreads();
    CP_WAIT(0); __syncthreads();           // G3 done
    k2_gemm(acc, sbu, 1, m0, n0, lane);    // chunk 3

    // Epilogue: bias + relu + direct store, out[b][d][node]
    #pragma unroll
    for (int mi = 0; mi < 2; mi++) {
        int mr = m0 + mi*16 + r;
        float bias_a = b2v[mr], bias_b = b2v[mr + 8];
        #pragma unroll
        for (int ni = 0; ni < 8; ni++) {
            int nc = n0 + ni*8 + c;
            int colA = col0 + nc, colB = colA + 1;
            int ba = colA / Nn, bb = colB / Nn;
            size_t obA = (size_t)ba * CO * Nn + (colA - ba * Nn);
            size_t obB = (size_t)bb * CO * Nn + (colB - bb * Nn);
            out[obA + (size_t)mr * Nn]     = fmaxf(acc[mi][ni][0] + bias_a, 0.f);
            out[obB + (size_t)mr * Nn]     = fmaxf(acc[mi][ni][1] + bias_a, 0.f);
            out[obA + (size_t)(mr+8) * Nn] = fmaxf(acc[mi][ni][2] + bias_b, 0.f);
            out[obB + (size_t)(mr+8) * Nn] = fmaxf(acc[mi][ni][3] + bias_b, 0.f);
        }
    }
}

// ---------------------------------------------------------------------------
extern "C" void kernel_launch(void* const* d_in, const int* in_sizes, int n_in,
                              void* d_out, int out_size)
{
    const float* x  = (const float*)d_in[0];
    const int*   ei = (const int*)  d_in[1];
    const float* W1 = (const float*)d_in[2];
    const float* b1 = (const float*)d_in[3];
    const float* Wp = (const float*)d_in[4];
    const float* bp = (const float*)d_in[5];
    const float* W2 = (const float*)d_in[6];
    const float* b2 = (const float*)d_in[7];
    float* out = (float*)d_out;

    const int s1 = 174592;
    const int s2 = 2 * K2_STAGE;      // 110592
    cudaFuncSetAttribute(k1, cudaFuncAttributeMaxDynamicSharedMemorySize, s1);
    cudaFuncSetAttribute(k2, cudaFuncAttributeMaxDynamicSharedMemorySize, s2);

    kw<<<384, 256>>>(W1, Wp, W2);
    k1<<<NT / 128, 512, s1>>>(x, b1, bp);
    k2<<<NT / 128, 512, s2>>>(ei, b2, out);
}

// round 12
// speedup vs baseline: 2.2477x; 1.3425x over previous
#include <cuda_runtime.h>
#include <cuda_bf16.h>
#include <cuda_fp16.h>
#include <cstdint>

#define Bb 8
#define Cc 128
#define Nn 10000
#define Kk 16
#define CO 256
#define NT (Bb*Nn)
#define S1 136              // k1 padded smem stride (halves) -> 272B rows, uint4-aligned
#define SK 72               // k2 chunk stride (64 k-elems + 8 pad)

// ---------------------------------------------------------------------------
// Device scratch (all fp16)
// ---------------------------------------------------------------------------
__device__ __align__(16) __half g_w1h[16384];
__device__ __align__(16) __half g_wph[16384];
__device__ __align__(16) __half g_w2h[65536];
__device__ __align__(16) __half g_cat[(size_t)NT*128];        // h, fp16
__device__ __align__(16) __half g_q[(size_t)NT*128];          // q, fp16

// D(16x8,f32) += A(16x16,fp16 row) * B(16x8,fp16 col)
__device__ __forceinline__ void mma_f16(float* d, const uint32_t* a, const uint32_t* b) {
    asm("mma.sync.aligned.m16n8k16.row.col.f32.f16.f16.f32 "
        "{%0,%1,%2,%3}, {%4,%5,%6,%7}, {%8,%9}, {%0,%1,%2,%3};"
        : "+f"(d[0]), "+f"(d[1]), "+f"(d[2]), "+f"(d[3])
        : "r"(a[0]), "r"(a[1]), "r"(a[2]), "r"(a[3]), "r"(b[0]), "r"(b[1]));
}

// ldmatrix x4: lane L supplies addr of row (L&15), k-half (L>>4)
__device__ __forceinline__ void ldm4(uint32_t r[4], uint32_t addr) {
    asm volatile("ldmatrix.sync.aligned.m8n8.x4.shared.b16 {%0,%1,%2,%3}, [%4];"
        : "=r"(r[0]), "=r"(r[1]), "=r"(r[2]), "=r"(r[3]) : "r"(addr));
}

__device__ __forceinline__ uint32_t s2u(const void* p) {
    uint32_t a;
    asm("{ .reg .u64 t; cvta.to.shared.u64 t, %1; cvt.u32.u64 %0, t; }" : "=r"(a) : "l"(p));
    return a;
}
__device__ __forceinline__ void cp16(uint32_t dst, const void* src) {
    asm volatile("cp.async.cg.shared.global [%0], [%1], 16;" :: "r"(dst), "l"(src));
}
#define CP_COMMIT() asm volatile("cp.async.commit_group;" ::: "memory")
#define CP_WAIT(N)  asm volatile("cp.async.wait_group %0;" :: "n"(N) : "memory")

// Warp GEMM, tile 32(M) x 32(N), K=128, single-term fp16, ldmatrix frags.
// aA/aB = smem byte addresses of A (weights, [m][k]) and B (nodes, [n][k]).
__device__ __forceinline__ void gemm_f16_2x4(float acc[2][4][4],
        uint32_t aA, uint32_t aB, int m0, int n0, int lane)
{
    const int rowA = lane & 15, khalf = (lane >> 4) * 8;
    #pragma unroll
    for (int kk = 0; kk < 8; kk++) {
        const int k0 = kk * 16;
        uint32_t a[2][4];
        #pragma unroll
        for (int mi = 0; mi < 2; mi++)
            ldm4(a[mi], aA + (uint32_t)(((m0 + mi*16 + rowA) * S1 + k0 + khalf) * 2));
        #pragma unroll
        for (int np = 0; np < 2; np++) {
            uint32_t bm[4];
            ldm4(bm, aB + (uint32_t)(((n0 + np*16 + rowA) * S1 + k0 + khalf) * 2));
            uint32_t b0[2] = {bm[0], bm[2]}, b1[2] = {bm[1], bm[3]};
            #pragma unroll
            for (int mi = 0; mi < 2; mi++) {
                mma_f16(acc[mi][2*np],   a[mi], b0);
                mma_f16(acc[mi][2*np+1], a[mi], b1);
            }
        }
    }
}

// ---------------------------------------------------------------------------
// kw: one-time fp16 conversion of all weights
// ---------------------------------------------------------------------------
__global__ void kw(const float* __restrict__ W1, const float* __restrict__ Wp,
                   const float* __restrict__ W2) {
    int t = blockIdx.x * 256 + threadIdx.x;     // 98304
    if (t < 16384)       g_w1h[t] = __float2half_rn(W1[t]);
    else if (t < 32768)  g_wph[t - 16384] = __float2half_rn(Wp[t - 16384]);
    else                 g_w2h[t - 32768] = __float2half_rn(W2[t - 32768]);
}

// ---------------------------------------------------------------------------
// k1: per 128-node tile: h = relu(W1@x+b1); q = relu(Wp@h+bp)
//     h -> g_cat (fp16), q -> g_q (fp16). 512 threads, 16 warps, 2 CTAs/SM.
// smem: [xb 512][W fp16 34816][B fp16 34816] = 70144
// ---------------------------------------------------------------------------
__global__ __launch_bounds__(512, 2)
void k1(const float* __restrict__ x, const float* __restrict__ b1v,
        const float* __restrict__ bpv)
{
    extern __shared__ unsigned char sm[];
    const uint32_t sbu = s2u(sm);
    int* xb = (int*)sm;
    __half* W  = (__half*)(sm + 512);
    __half* Bf = (__half*)(sm + 512 + 34816);
    __half* Qh = W;                       // overlay after GEMM2
    const uint32_t aW = sbu + 512, aB = aW + 34816;

    const int tid = threadIdx.x, lane = tid & 31, wid = tid >> 5;
    const int r = lane >> 2, c = (lane & 3) * 2;
    const int m0 = (wid >> 2) * 32, n0 = (wid & 3) * 32;
    const int col0 = blockIdx.x * 128;

    if (tid < 128) {
        int col = col0 + tid, b = col / Nn;
        xb[tid] = b * (Cc * Nn) + (col - b * Nn);
    }
    {   // W1 -> smem (uint32, padded stride)
        const uint32_t* s = (const uint32_t*)g_w1h;
        uint32_t* d = (uint32_t*)W;
        #pragma unroll 4
        for (int i = tid; i < 8192; i += 512) {
            int m = i >> 6, w = i & 63;
            d[m*68 + w] = s[i];
        }
    }
    __syncthreads();

    // x tile -> B plane (node-major, fp16)
    for (int i = tid; i < 16384; i += 512) {
        int j = i & 127, ch = i >> 7;
        Bf[j*S1 + ch] = __float2half_rn(x[xb[j] + ch * Nn]);
    }
    __syncthreads();

    float acc[2][4][4];
    #pragma unroll
    for (int i = 0; i < 2; i++)
        #pragma unroll
        for (int j = 0; j < 4; j++)
            #pragma unroll
            for (int v = 0; v < 4; v++) acc[i][j][v] = 0.f;

    gemm_f16_2x4(acc, aW, aB, m0, n0, lane);
    __syncthreads();

    // Epilogue 1: h -> B plane (fp16, in place over x) ; Wp -> W plane
    #pragma unroll
    for (int mi = 0; mi < 2; mi++) {
        int mr = m0 + mi*16 + r;
        float bias_a = b1v[mr], bias_b = b1v[mr + 8];
        #pragma unroll
        for (int ni = 0; ni < 4; ni++) {
            int nc = n0 + ni*8 + c;
            Bf[nc*S1 + mr]       = __float2half_rn(fmaxf(acc[mi][ni][0] + bias_a, 0.f));
            Bf[(nc+1)*S1 + mr]   = __float2half_rn(fmaxf(acc[mi][ni][1] + bias_a, 0.f));
            Bf[nc*S1 + mr+8]     = __float2half_rn(fmaxf(acc[mi][ni][2] + bias_b, 0.f));
            Bf[(nc+1)*S1 + mr+8] = __float2half_rn(fmaxf(acc[mi][ni][3] + bias_b, 0.f));
        }
    }
    {   // Wp -> W plane
        const uint32_t* s = (const uint32_t*)g_wph;
        uint32_t* d = (uint32_t*)W;
        #pragma unroll 4
        for (int i = tid; i < 8192; i += 512) {
            int m = i >> 6, w = i & 63;
            d[m*68 + w] = s[i];
        }
    }
    __syncthreads();

    // h rows -> g_cat (coalesced uint4)
    for (int i = tid; i < 2048; i += 512) {
        int j = i >> 4, v = i & 15;
        ((uint4*)(g_cat + (size_t)(col0 + j) * 128))[v] = ((const uint4*)(Bf + j*S1))[v];
    }

    #pragma unroll
    for (int i = 0; i < 2; i++)
        #pragma unroll
        for (int j = 0; j < 4; j++)
            #pragma unroll
            for (int v = 0; v < 4; v++) acc[i][j][v] = 0.f;

    gemm_f16_2x4(acc, aW, aB, m0, n0, lane);
    __syncthreads();      // W reads done; Qh may overlay

    // Epilogue 2: q -> Qh staging (fp16, stride S1)
    #pragma unroll
    for (int mi = 0; mi < 2; mi++) {
        int mr = m0 + mi*16 + r;
        float bias_a = bpv[mr], bias_b = bpv[mr + 8];
        #pragma unroll
        for (int ni = 0; ni < 4; ni++) {
            int nc = n0 + ni*8 + c;
            Qh[nc*S1 + mr]       = __float2half_rn(fmaxf(acc[mi][ni][0] + bias_a, 0.f));
            Qh[(nc+1)*S1 + mr]   = __float2half_rn(fmaxf(acc[mi][ni][1] + bias_a, 0.f));
            Qh[nc*S1 + mr+8]     = __float2half_rn(fmaxf(acc[mi][ni][2] + bias_b, 0.f));
            Qh[(nc+1)*S1 + mr+8] = __float2half_rn(fmaxf(acc[mi][ni][3] + bias_b, 0.f));
        }
    }
    __syncthreads();

    // q -> g_q (coalesced uint4)
    for (int i = tid; i < 2048; i += 512) {
        int j = i >> 4, v = i & 15;
        ((uint4*)(g_q + (size_t)(col0 + j) * 128))[v] = ((const uint4*)(Qh + j*S1))[v];
    }
}

// ---------------------------------------------------------------------------
// k2: out = relu(W2 @ cat + b2), single-term fp16 MMA.
// M=256, N=128/block. K=256 in 4 chunks of 64, double-buffered cp.async;
// chunks 2,3 B operand gathered in-kernel from g_q (fp16, hmax2).
// stage: [A 256xSK fp16 36864][B 128xSK fp16 18432] = 55296; x2 = 110592
// ---------------------------------------------------------------------------
#define K2_STAGE 55296
#define K2_B 36864

__device__ __forceinline__ void k2_load_a(uint32_t sbu, int stage, int ks, int tid) {
    const uint32_t base = sbu + stage * K2_STAGE;
    #pragma unroll
    for (int t = 0; t < 4; t++) {
        int i = tid + t * 512;           // 0..2047
        int m = i >> 3, ch = i & 7;
        cp16(base + (uint32_t)(m * SK + ch * 8) * 2, g_w2h + m * 256 + ks * 64 + ch * 8);
    }
}
__device__ __forceinline__ void k2_load_b_cat(uint32_t sbu, int stage, int ks,
                                              int col0, int tid) {
    const uint32_t base = sbu + stage * K2_STAGE + K2_B;
    #pragma unroll
    for (int t = 0; t < 2; t++) {
        int i = tid + t * 512;           // 0..1023
        int j = i >> 3, ch = i & 7;
        cp16(base + (uint32_t)(j * SK + ch * 8) * 2,
             g_cat + (size_t)(col0 + j) * 128 + ks * 64 + ch * 8);
    }
}

// gather-max 128 nodes x 128 ch (fp16). Round t: warp gets node wid+16t;
// lane covers ch = lane*4 (uint2 = 4 fp16).
__device__ __forceinline__ void k2_gather(const int* __restrict__ eidx, int col0,
                                          int wid, int lane, uint2 g[8]) {
    #pragma unroll
    for (int t = 0; t < 8; t++) {
        int col = col0 + wid + 16 * t;
        int b = col / Nn;
        const __half* qb = g_q + (size_t)b * Nn * 128;
        int id = 0;
        if (lane < Kk) id = eidx[col * Kk + lane];
        __half2 m0 = __half2{__half(0.f), __half(0.f)}, m1 = m0;   // q >= 0
        #pragma unroll
        for (int k = 0; k < Kk; k++) {
            int nb = __shfl_sync(0xffffffffu, id, k);
            uint2 v = *(const uint2*)(qb + (size_t)nb * 128 + lane * 4);
            m0 = __hmax2(m0, *(__half2*)&v.x);
            m1 = __hmax2(m1, *(__half2*)&v.y);
        }
        g[t] = make_uint2(*(uint32_t*)&m0, *(uint32_t*)&m1);
    }
}

// lanes 0-15 hold chunk2 (half=0), lanes 16-31 chunk3 (half=1)
__device__ __forceinline__ void k2_store_gather(unsigned char* sm, int stage, int half,
                                                const uint2 g[8], int wid, int lane) {
    if ((lane >> 4) != half) return;
    const int kloc = (lane & 15) * 4;
    unsigned char* B = sm + stage * K2_STAGE + K2_B;
    #pragma unroll
    for (int t = 0; t < 8; t++) {
        int j = wid + 16 * t;
        *(uint2*)(B + (j * SK + kloc) * 2) = g[t];
    }
}

// one K=64 chunk, single-term fp16, ldmatrix fragments
__device__ __forceinline__ void k2_gemm(float acc[2][8][4], uint32_t sbu,
                                        int stage, int m0, int n0, int lane) {
    const uint32_t st = sbu + stage * K2_STAGE;
    const int rowA = lane & 15, khalf = (lane >> 4) * 8;
    #pragma unroll
    for (int kk = 0; kk < 4; kk++) {
        const int k0 = kk * 16;
        uint32_t a[2][4];
        #pragma unroll
        for (int mi = 0; mi < 2; mi++)
            ldm4(a[mi], st + (uint32_t)(((m0 + mi*16 + rowA) * SK + k0 + khalf) * 2));
        #pragma unroll
        for (int np = 0; np < 4; np++) {
            uint32_t bm[4];
            ldm4(bm, st + K2_B + (uint32_t)(((n0 + np*16 + rowA) * SK + k0 + khalf) * 2));
            uint32_t b0[2] = {bm[0], bm[2]}, b1[2] = {bm[1], bm[3]};
            #pragma unroll
            for (int mi = 0; mi < 2; mi++) {
                mma_f16(acc[mi][2*np],   a[mi], b0);
                mma_f16(acc[mi][2*np+1], a[mi], b1);
            }
        }
    }
}

__global__ __launch_bounds__(512)
void k2(const int* __restrict__ eidx, const float* __restrict__ b2v,
        float* __restrict__ out)
{
    extern __shared__ unsigned char sm[];
    const uint32_t sbu = s2u(sm);
    const int tid = threadIdx.x, lane = tid & 31, wid = tid >> 5;
    const int r = lane >> 2, c = (lane & 3) * 2;
    const int m0 = (wid >> 1) * 32, n0 = (wid & 1) * 64;
    const int col0 = blockIdx.x * 128;

    // Prefetch chunks 0,1 (A = W2 slices; B = h from g_cat)
    k2_load_a(sbu, 0, 0, tid); k2_load_b_cat(sbu, 0, 0, col0, tid); CP_COMMIT(); // G0
    k2_load_a(sbu, 1, 1, tid); k2_load_b_cat(sbu, 1, 1, col0, tid); CP_COMMIT(); // G1

    // Gather chunks 2,3 into registers (overlaps G0/G1 arrival)
    uint2 g[8];
    k2_gather(eidx, col0, wid, lane, g);

    float acc[2][8][4];
    #pragma unroll
    for (int i = 0; i < 2; i++)
        #pragma unroll
        for (int j = 0; j < 8; j++)
            #pragma unroll
            for (int v = 0; v < 4; v++) acc[i][j][v] = 0.f;

    CP_WAIT(1); __syncthreads();           // G0 done
    k2_gemm(acc, sbu, 0, m0, n0, lane);    // chunk 0
    __syncthreads();                       // stage0 B free

    k2_store_gather(sm, 0, 0, g, wid, lane);   // chunk2 -> B(st0)
    k2_load_a(sbu, 0, 2, tid); CP_COMMIT();    // G2 (A only)
    CP_WAIT(1); __syncthreads();           // G1 done
    k2_gemm(acc, sbu, 1, m0, n0, lane);    // chunk 1
    __syncthreads();                       // stage1 B free

    k2_store_gather(sm, 1, 1, g, wid, lane);   // chunk3 -> B(st1)
    k2_load_a(sbu, 1, 3, tid); CP_COMMIT();    // G3
    CP_WAIT(1); __syncthreads();           // G2 done (+ STS visible)
    k2_gemm(acc, sbu, 0, m0, n0, lane);    // chunk 2
    __syncthreads();
    CP_WAIT(0); __syncthreads();           // G3 done
    k2_gemm(acc, sbu, 1, m0, n0, lane);    // chunk 3

    // Epilogue: bias + relu + direct store, out[b][d][node]
    #pragma unroll
    for (int mi = 0; mi < 2; mi++) {
        int mr = m0 + mi*16 + r;
        float bias_a = b2v[mr], bias_b = b2v[mr + 8];
        #pragma unroll
        for (int ni = 0; ni < 8; ni++) {
            int nc = n0 + ni*8 + c;
            int colA = col0 + nc, colB = colA + 1;
            int ba = colA / Nn, bb = colB / Nn;
            size_t obA = (size_t)ba * CO * Nn + (colA - ba * Nn);
            size_t obB = (size_t)bb * CO * Nn + (colB - bb * Nn);
            out[obA + (size_t)mr * Nn]     = fmaxf(acc[mi][ni][0] + bias_a, 0.f);
            out[obB + (size_t)mr * Nn]     = fmaxf(acc[mi][ni][1] + bias_a, 0.f);
            out[obA + (size_t)(mr+8) * Nn] = fmaxf(acc[mi][ni][2] + bias_b, 0.f);
            out[obB + (size_t)(mr+8) * Nn] = fmaxf(acc[mi][ni][3] + bias_b, 0.f);
        }
    }
}

// ---------------------------------------------------------------------------
extern "C" void kernel_launch(void* const* d_in, const int* in_sizes, int n_in,
                              void* d_out, int out_size)
{
    const float* x  = (const float*)d_in[0];
    const int*   ei = (const int*)  d_in[1];
    const float* W1 = (const float*)d_in[2];
    const float* b1 = (const float*)d_in[3];
    const float* Wp = (const float*)d_in[4];
    const float* bp = (const float*)d_in[5];
    const float* W2 = (const float*)d_in[6];
    const float* b2 = (const float*)d_in[7];
    float* out = (float*)d_out;

    const int s1 = 70144;
    const int s2 = 2 * K2_STAGE;      // 110592
    cudaFuncSetAttribute(k1, cudaFuncAttributeMaxDynamicSharedMemorySize, s1);
    cudaFuncSetAttribute(k2, cudaFuncAttributeMaxDynamicSharedMemorySize, s2);

    kw<<<384, 256>>>(W1, Wp, W2);
    k1<<<NT / 128, 512, s1>>>(x, b1, bp);
    k2<<<NT / 128, 512, s2>>>(ei, b2, out);
}